// round 5
// baseline (speedup 1.0000x reference)
#include <cuda_runtime.h>
#include <math.h>

// Collapsed classifier vectors: wv[c][d] = sum_j Wf[c,j] * W1[j,d],
// cc[c] = bf[c] + sum_j Wf[c,j] * b1[j]
__device__ float g_wv[2][128];
__device__ float g_cc[2];

// ---------------- packed f32x2 helpers ----------------
__device__ __forceinline__ unsigned long long dup2(float x) {
    unsigned long long r;
    asm("mov.b64 %0, {%1, %1};" : "=l"(r) : "f"(x));
    return r;
}
__device__ __forceinline__ void fma2(unsigned long long& d,
                                     unsigned long long a,
                                     unsigned long long b) {
    asm("fma.rn.f32x2 %0, %1, %2, %0;" : "+l"(d) : "l"(a), "l"(b));
}
__device__ __forceinline__ float2 unpack2(unsigned long long v) {
    float2 r;
    asm("mov.b64 {%0, %1}, %2;" : "=f"(r.x), "=f"(r.y) : "l"(v));
    return r;
}

// ---------------- prep: collapse W1/Wf/b1/bf ----------------
__global__ void prep_kernel(const float* __restrict__ W1,
                            const float* __restrict__ Wf,
                            const float* __restrict__ b1,
                            const float* __restrict__ bf) {
    int t = threadIdx.x;           // 256 threads: (c,d)
    int c = t >> 7;
    int d = t & 127;
    double s = 0.0;
    for (int j = 0; j < 128; j++)
        s += (double)Wf[c * 128 + j] * (double)W1[j * 128 + d];
    g_wv[c][d] = (float)s;
    if (t < 2) {
        double cs = 0.0;
        for (int j = 0; j < 128; j++)
            cs += (double)Wf[t * 128 + j] * (double)b1[j];
        g_cc[t] = (float)(cs + (double)bf[t]);
    }
}

// ---------------- main fused kernel ----------------
// Block: 128 edges x 128 hidden outputs. 256 threads = 16(tx: d' groups) x 16(ty: edge groups).
// Each thread: 8 edges (as 4 f32x2 pairs) x 8 d' accumulators.
__global__ void __launch_bounds__(256, 1)
advers_mask_edge_kernel(const float* __restrict__ h,
                        const float* __restrict__ W0,
                        const float* __restrict__ b0,
                        const float* __restrict__ u,
                        const int* __restrict__ src,
                        const int* __restrict__ dst,
                        float* __restrict__ out,
                        int E, int N) {
    extern __shared__ float smem_f[];
    float* sp = smem_f;            // [128 k][128 e] product tile (64 KB)
    float* wb = smem_f + 16384;    // [128 k][128 dp] W0 segment, k-major (64 KB)

    const int tid = threadIdx.x;
    const int tx  = tid & 15;      // d' group
    const int ty  = tid >> 4;      // edge group
    const int eb  = blockIdx.x * 128;

    // gather indices once (same for all 4 segments)
    const int el   = tid >> 1;     // 0..127: edge (for sp build) / dp row (for wb build)
    const int half = tid & 1;      // which 64-d half this thread loads
    int eg = eb + el;
    int ec = (eg < E) ? eg : (E - 1);
    const int se = src[ec];
    const int de = dst[ec];

    unsigned long long acc[4][8];
#pragma unroll
    for (int i = 0; i < 4; i++)
#pragma unroll
        for (int j = 0; j < 8; j++) acc[i][j] = 0ull;

    const float* sprow = sp + ty * 8;
    const float* wrow  = wb + tx * 8;

    for (int seg = 0; seg < 4; seg++) {
        const int l0 = seg >> 1;
        const int l1 = seg & 1;
        if (seg) __syncthreads();   // previous GEMM done reading smem

        // ---- build product tile sp[k][e] = h[l0,src[e],k] * h[l1,dst[e],k] ----
        {
            const float* hs = h + ((size_t)l0 * N + se) * 128;
            const float* hd = h + ((size_t)l1 * N + de) * 128;
#pragma unroll
            for (int q = 0; q < 16; q++) {
                int d = half * 64 + q * 4;
                float4 va = *(const float4*)(hs + d);
                float4 vb = *(const float4*)(hd + d);
                sp[(d + 0) * 128 + el] = va.x * vb.x;
                sp[(d + 1) * 128 + el] = va.y * vb.y;
                sp[(d + 2) * 128 + el] = va.z * vb.z;
                sp[(d + 3) * 128 + el] = va.w * vb.w;
            }
        }
        // ---- load W0 segment transposed: wb[k][dp] = W0[dp, seg*128 + k] ----
        {
            const float* ws = W0 + (size_t)el * 512 + seg * 128;
#pragma unroll
            for (int q = 0; q < 16; q++) {
                int kk = half * 64 + q * 4;
                float4 wv4 = *(const float4*)(ws + kk);
                wb[(kk + 0) * 128 + el] = wv4.x;
                wb[(kk + 1) * 128 + el] = wv4.y;
                wb[(kk + 2) * 128 + el] = wv4.z;
                wb[(kk + 3) * 128 + el] = wv4.w;
            }
        }
        __syncthreads();

        // ---- 128x128x128 f32x2 GEMM accumulate ----
#pragma unroll 4
        for (int k = 0; k < 128; k++) {
            ulonglong2 a0 = *(const ulonglong2*)(sprow + k * 128);      // edges 0..3 (2 pairs)
            ulonglong2 a1 = *(const ulonglong2*)(sprow + k * 128 + 4);  // edges 4..7
            float4 w0 = *(const float4*)(wrow + k * 128);
            float4 w1 = *(const float4*)(wrow + k * 128 + 4);
            unsigned long long bd0 = dup2(w0.x), bd1 = dup2(w0.y);
            unsigned long long bd2 = dup2(w0.z), bd3 = dup2(w0.w);
            unsigned long long bd4 = dup2(w1.x), bd5 = dup2(w1.y);
            unsigned long long bd6 = dup2(w1.z), bd7 = dup2(w1.w);
            fma2(acc[0][0], a0.x, bd0); fma2(acc[0][1], a0.x, bd1);
            fma2(acc[0][2], a0.x, bd2); fma2(acc[0][3], a0.x, bd3);
            fma2(acc[0][4], a0.x, bd4); fma2(acc[0][5], a0.x, bd5);
            fma2(acc[0][6], a0.x, bd6); fma2(acc[0][7], a0.x, bd7);
            fma2(acc[1][0], a0.y, bd0); fma2(acc[1][1], a0.y, bd1);
            fma2(acc[1][2], a0.y, bd2); fma2(acc[1][3], a0.y, bd3);
            fma2(acc[1][4], a0.y, bd4); fma2(acc[1][5], a0.y, bd5);
            fma2(acc[1][6], a0.y, bd6); fma2(acc[1][7], a0.y, bd7);
            fma2(acc[2][0], a1.x, bd0); fma2(acc[2][1], a1.x, bd1);
            fma2(acc[2][2], a1.x, bd2); fma2(acc[2][3], a1.x, bd3);
            fma2(acc[2][4], a1.x, bd4); fma2(acc[2][5], a1.x, bd5);
            fma2(acc[2][6], a1.x, bd6); fma2(acc[2][7], a1.x, bd7);
            fma2(acc[3][0], a1.y, bd0); fma2(acc[3][1], a1.y, bd1);
            fma2(acc[3][2], a1.y, bd2); fma2(acc[3][3], a1.y, bd3);
            fma2(acc[3][4], a1.y, bd4); fma2(acc[3][5], a1.y, bd5);
            fma2(acc[3][6], a1.y, bd6); fma2(acc[3][7], a1.y, bd7);
        }
    }

    // ---- epilogue: bias + relu + dual dot vs wv, reduce over tx, gumbel, argmax ----
    float wv0r[8], wv1r[8], bbr[8];
#pragma unroll
    for (int j = 0; j < 8; j++) {
        int dp = tx * 8 + j;
        wv0r[j] = g_wv[0][dp];
        wv1r[j] = g_wv[1][dp];
        bbr[j]  = b0[dp];
    }
    const float cc0 = g_cc[0];
    const float cc1 = g_cc[1];

#pragma unroll
    for (int i = 0; i < 4; i++) {
        float s0a = 0.f, s1a = 0.f, s0b = 0.f, s1b = 0.f;
#pragma unroll
        for (int j = 0; j < 8; j++) {
            float2 xv = unpack2(acc[i][j]);
            float xa = fmaxf(xv.x + bbr[j], 0.f);
            float xb = fmaxf(xv.y + bbr[j], 0.f);
            s0a = fmaf(xa, wv0r[j], s0a);
            s1a = fmaf(xa, wv1r[j], s1a);
            s0b = fmaf(xb, wv0r[j], s0b);
            s1b = fmaf(xb, wv1r[j], s1b);
        }
        // reduce over the 16 tx lanes (contiguous half-warp; xor stays inside it)
#pragma unroll
        for (int off = 8; off; off >>= 1) {
            s0a += __shfl_xor_sync(0xffffffffu, s0a, off);
            s1a += __shfl_xor_sync(0xffffffffu, s1a, off);
            s0b += __shfl_xor_sync(0xffffffffu, s0b, off);
            s1b += __shfl_xor_sync(0xffffffffu, s1b, off);
        }
        if (tx == 0) {
            int e0 = eb + ty * 8 + i * 2;
#pragma unroll
            for (int lane = 0; lane < 2; lane++) {
                int e = e0 + lane;
                if (e < E) {
                    float s0 = lane ? s0b : s0a;
                    float s1 = lane ? s1b : s1a;
                    float u0 = u[2 * e];
                    float u1 = u[2 * e + 1];
                    float gg0 = -logf(-logf(u0 + 1e-10f) + 1e-10f);
                    float gg1 = -logf(-logf(u1 + 1e-10f) + 1e-10f);
                    float v0 = s0 + cc0 + gg0;
                    float v1 = s1 + cc1 + gg1;
                    // jnp.argmax ties -> index 0; class 1 only if strictly greater
                    bool one = (v1 > v0);
                    out[2 * e]     = one ? 0.f : 1.f;
                    out[2 * e + 1] = one ? 1.f : 0.f;
                }
            }
        }
    }
}

extern "C" void kernel_launch(void* const* d_in, const int* in_sizes, int n_in,
                              void* d_out, int out_size) {
    const float* h  = (const float*)d_in[0];
    const float* W0 = (const float*)d_in[1];
    const float* b0 = (const float*)d_in[2];
    const float* W1 = (const float*)d_in[3];
    const float* b1 = (const float*)d_in[4];
    const float* Wf = (const float*)d_in[5];
    const float* bf = (const float*)d_in[6];
    const float* u  = (const float*)d_in[7];
    const int*   src = (const int*)d_in[8];
    const int*   dst = (const int*)d_in[9];
    float* out = (float*)d_out;

    const int E = in_sizes[8];
    const int N = in_sizes[0] / 256;   // h is (L=2, N, D=128)

    prep_kernel<<<1, 256>>>(W1, Wf, b1, bf);

    const size_t smem = (size_t)(16384 + 16384) * sizeof(float);  // 128 KB
    cudaFuncSetAttribute(advers_mask_edge_kernel,
                         cudaFuncAttributeMaxDynamicSharedMemorySize, (int)smem);

    int blocks = (E + 127) / 128;
    advers_mask_edge_kernel<<<blocks, 256, smem>>>(h, W0, b0, u, src, dst, out, E, N);
}

// round 6
// speedup vs baseline: 1.0751x; 1.0751x over previous
#include <cuda_runtime.h>
#include <math.h>

// Collapsed classifier vectors: wv[c][d] = sum_j Wf[c,j] * W1[j,d],
// cc[c] = bf[c] + sum_j Wf[c,j] * b1[j]
__device__ float g_wv[2][128];
__device__ float g_cc[2];

// ---------------- packed f32x2 helpers ----------------
__device__ __forceinline__ unsigned long long dup2(float x) {
    unsigned long long r;
    asm("mov.b64 %0, {%1, %1};" : "=l"(r) : "f"(x));
    return r;
}
__device__ __forceinline__ void fma2(unsigned long long& d,
                                     unsigned long long a,
                                     unsigned long long b) {
    asm("fma.rn.f32x2 %0, %1, %2, %0;" : "+l"(d) : "l"(a), "l"(b));
}
__device__ __forceinline__ float2 unpack2(unsigned long long v) {
    float2 r;
    asm("mov.b64 {%0, %1}, %2;" : "=f"(r.x), "=f"(r.y) : "l"(v));
    return r;
}

// ---------------- prep: collapse W1/Wf/b1/bf ----------------
__global__ void prep_kernel(const float* __restrict__ W1,
                            const float* __restrict__ Wf,
                            const float* __restrict__ b1,
                            const float* __restrict__ bf) {
    int t = threadIdx.x;           // 256 threads: (c,d)
    int c = t >> 7;
    int d = t & 127;
    double s = 0.0;
    for (int j = 0; j < 128; j++)
        s += (double)Wf[c * 128 + j] * (double)W1[j * 128 + d];
    g_wv[c][d] = (float)s;
    if (t < 2) {
        double cs = 0.0;
        for (int j = 0; j < 128; j++)
            cs += (double)Wf[t * 128 + j] * (double)b1[j];
        g_cc[t] = (float)(cs + (double)bf[t]);
    }
}

// ---------------- main fused kernel ----------------
// Block: 128 edges x 128 hidden outputs, 256 threads = 16(tx: dp groups) x 16(ty: edge groups).
// Each thread: 8 edges (4 f32x2 pairs) x 8 dp accumulators.
// smem: sp[128k][128e] product tile (64KB) + wb[64k][128dp] W0 chunk (32KB) = 96KB
//   wb layout: float index k*128 + c*64 + tx*4 + r  <->  W0[dp = tx*8 + c*4 + r][segbase + k]
//   => GEMM W loads are 16 threads x 16B CONTIGUOUS 256B per LDS.128 (conflict-free).
__global__ void __launch_bounds__(256, 2)
advers_mask_edge_kernel(const float* __restrict__ h,
                        const float* __restrict__ W0,
                        const float* __restrict__ b0,
                        const float* __restrict__ u,
                        const int* __restrict__ src,
                        const int* __restrict__ dst,
                        float* __restrict__ out,
                        int E, int N) {
    extern __shared__ float smem_f[];
    float* sp = smem_f;            // [128][128]
    float* wb = smem_f + 16384;    // [64][128] (k-chunk)

    const int tid = threadIdx.x;
    const int tx  = tid & 15;      // dp group
    const int ty  = tid >> 4;      // edge group
    const int eb  = blockIdx.x * 128;

    const int el   = tid >> 1;     // 0..127: edge (sp build) / dp row (wb build)
    const int half = tid & 1;
    // wb store target for dp = el
    const int wdst = ((el >> 2) & 1) * 64 + (el >> 3) * 4 + (el & 3);

    int eg = eb + el;
    int ec = (eg < E) ? eg : (E - 1);
    const int se = src[ec];
    const int de = dst[ec];

    unsigned long long acc[4][8];
#pragma unroll
    for (int i = 0; i < 4; i++)
#pragma unroll
        for (int j = 0; j < 8; j++) acc[i][j] = 0ull;

    for (int seg = 0; seg < 4; seg++) {
        const int l0 = seg >> 1;
        const int l1 = seg & 1;
        if (seg) __syncthreads();   // previous chunk's GEMM done reading sp/wb

        // ---- build product tile sp[k][e] = h[l0,src[e],k] * h[l1,dst[e],k] ----
        {
            const float* hs = h + ((size_t)l0 * N + se) * 128;
            const float* hd = h + ((size_t)l1 * N + de) * 128;
#pragma unroll
            for (int q = 0; q < 16; q++) {
                int d = half * 64 + q * 4;
                float4 va = *(const float4*)(hs + d);
                float4 vb = *(const float4*)(hd + d);
                sp[(d + 0) * 128 + el] = va.x * vb.x;
                sp[(d + 1) * 128 + el] = va.y * vb.y;
                sp[(d + 2) * 128 + el] = va.z * vb.z;
                sp[(d + 3) * 128 + el] = va.w * vb.w;
            }
        }

        for (int ch = 0; ch < 2; ch++) {
            if (ch) __syncthreads();  // chunk-0 GEMM done reading wb

            // ---- build W chunk: wb <- W0[dp][seg*128 + ch*64 + k], k in [0,64) ----
            {
                const float* ws = W0 + (size_t)el * 512 + seg * 128 + ch * 64 + half * 32;
#pragma unroll
                for (int q = 0; q < 8; q++) {
                    float4 w4 = *(const float4*)(ws + q * 4);
                    int kk = half * 32 + q * 4;
                    wb[(kk + 0) * 128 + wdst] = w4.x;
                    wb[(kk + 1) * 128 + wdst] = w4.y;
                    wb[(kk + 2) * 128 + wdst] = w4.z;
                    wb[(kk + 3) * 128 + wdst] = w4.w;
                }
            }
            __syncthreads();

            // ---- 128e x 128dp x 64k f32x2 GEMM accumulate ----
            const float* sprow = sp + ch * (64 * 128) + ty * 8;
            const float* wrow  = wb + tx * 4;
#pragma unroll 2
            for (int k = 0; k < 64; k++) {
                ulonglong2 a0 = *(const ulonglong2*)(sprow + k * 128);      // edges 0..3
                ulonglong2 a1 = *(const ulonglong2*)(sprow + k * 128 + 4);  // edges 4..7
                float4 w0 = *(const float4*)(wrow + k * 128);       // dp tx*8+0..3
                float4 w1 = *(const float4*)(wrow + k * 128 + 64);  // dp tx*8+4..7
                unsigned long long bd0 = dup2(w0.x), bd1 = dup2(w0.y);
                unsigned long long bd2 = dup2(w0.z), bd3 = dup2(w0.w);
                unsigned long long bd4 = dup2(w1.x), bd5 = dup2(w1.y);
                unsigned long long bd6 = dup2(w1.z), bd7 = dup2(w1.w);
                fma2(acc[0][0], a0.x, bd0); fma2(acc[0][1], a0.x, bd1);
                fma2(acc[0][2], a0.x, bd2); fma2(acc[0][3], a0.x, bd3);
                fma2(acc[0][4], a0.x, bd4); fma2(acc[0][5], a0.x, bd5);
                fma2(acc[0][6], a0.x, bd6); fma2(acc[0][7], a0.x, bd7);
                fma2(acc[1][0], a0.y, bd0); fma2(acc[1][1], a0.y, bd1);
                fma2(acc[1][2], a0.y, bd2); fma2(acc[1][3], a0.y, bd3);
                fma2(acc[1][4], a0.y, bd4); fma2(acc[1][5], a0.y, bd5);
                fma2(acc[1][6], a0.y, bd6); fma2(acc[1][7], a0.y, bd7);
                fma2(acc[2][0], a1.x, bd0); fma2(acc[2][1], a1.x, bd1);
                fma2(acc[2][2], a1.x, bd2); fma2(acc[2][3], a1.x, bd3);
                fma2(acc[2][4], a1.x, bd4); fma2(acc[2][5], a1.x, bd5);
                fma2(acc[2][6], a1.x, bd6); fma2(acc[2][7], a1.x, bd7);
                fma2(acc[3][0], a1.y, bd0); fma2(acc[3][1], a1.y, bd1);
                fma2(acc[3][2], a1.y, bd2); fma2(acc[3][3], a1.y, bd3);
                fma2(acc[3][4], a1.y, bd4); fma2(acc[3][5], a1.y, bd5);
                fma2(acc[3][6], a1.y, bd6); fma2(acc[3][7], a1.y, bd7);
            }
        }
    }

    // ---- epilogue: bias + relu + dual dot vs wv, reduce over tx, gumbel, argmax ----
    float wv0r[8], wv1r[8], bbr[8];
#pragma unroll
    for (int j = 0; j < 8; j++) {
        int dp = tx * 8 + j;
        wv0r[j] = g_wv[0][dp];
        wv1r[j] = g_wv[1][dp];
        bbr[j]  = b0[dp];
    }
    const float cc0 = g_cc[0];
    const float cc1 = g_cc[1];

#pragma unroll
    for (int i = 0; i < 4; i++) {
        float s0a = 0.f, s1a = 0.f, s0b = 0.f, s1b = 0.f;
#pragma unroll
        for (int j = 0; j < 8; j++) {
            float2 xv = unpack2(acc[i][j]);
            float xa = fmaxf(xv.x + bbr[j], 0.f);
            float xb = fmaxf(xv.y + bbr[j], 0.f);
            s0a = fmaf(xa, wv0r[j], s0a);
            s1a = fmaf(xa, wv1r[j], s1a);
            s0b = fmaf(xb, wv0r[j], s0b);
            s1b = fmaf(xb, wv1r[j], s1b);
        }
        // reduce over the 16 tx lanes (xor stays inside each 16-lane half-warp)
#pragma unroll
        for (int off = 8; off; off >>= 1) {
            s0a += __shfl_xor_sync(0xffffffffu, s0a, off);
            s1a += __shfl_xor_sync(0xffffffffu, s1a, off);
            s0b += __shfl_xor_sync(0xffffffffu, s0b, off);
            s1b += __shfl_xor_sync(0xffffffffu, s1b, off);
        }
        if (tx == 0) {
            int e0 = eb + ty * 8 + i * 2;
#pragma unroll
            for (int lane = 0; lane < 2; lane++) {
                int e = e0 + lane;
                if (e < E) {
                    float s0 = lane ? s0b : s0a;
                    float s1 = lane ? s1b : s1a;
                    float u0 = u[2 * e];
                    float u1 = u[2 * e + 1];
                    float gg0 = -logf(-logf(u0 + 1e-10f) + 1e-10f);
                    float gg1 = -logf(-logf(u1 + 1e-10f) + 1e-10f);
                    float v0 = s0 + cc0 + gg0;
                    float v1 = s1 + cc1 + gg1;
                    // jnp.argmax ties -> index 0; class 1 only if strictly greater
                    bool one = (v1 > v0);
                    out[2 * e]     = one ? 0.f : 1.f;
                    out[2 * e + 1] = one ? 1.f : 0.f;
                }
            }
        }
    }
}

extern "C" void kernel_launch(void* const* d_in, const int* in_sizes, int n_in,
                              void* d_out, int out_size) {
    const float* h  = (const float*)d_in[0];
    const float* W0 = (const float*)d_in[1];
    const float* b0 = (const float*)d_in[2];
    const float* W1 = (const float*)d_in[3];
    const float* b1 = (const float*)d_in[4];
    const float* Wf = (const float*)d_in[5];
    const float* bf = (const float*)d_in[6];
    const float* u  = (const float*)d_in[7];
    const int*   src = (const int*)d_in[8];
    const int*   dst = (const int*)d_in[9];
    float* out = (float*)d_out;

    const int E = in_sizes[8];
    const int N = in_sizes[0] / 256;   // h is (L=2, N, D=128)

    prep_kernel<<<1, 256>>>(W1, Wf, b1, bf);

    const size_t smem = (size_t)(16384 + 8192) * sizeof(float);  // 96 KB
    cudaFuncSetAttribute(advers_mask_edge_kernel,
                         cudaFuncAttributeMaxDynamicSharedMemorySize, (int)smem);

    int blocks = (E + 127) / 128;
    advers_mask_edge_kernel<<<blocks, 256, smem>>>(h, W0, b0, u, src, dst, out, E, N);
}